// round 1
// baseline (speedup 1.0000x reference)
#include <cuda_runtime.h>

// ConditionalPatchSlicedTransport — fused per-patch transport kernel.
//
// Constants from the reference:
//   N=2048 samples, NDIM=NTRANS=3072, 192 patches of 16 pixels, 16 comps,
//   10 classes, 200 spline knots.
//
// Pipeline:
//   prep_kernel:  class-sort sample indices (g_idx, g_off)
//   main_kernel:  block (patch k, class c): smem knots (16 transforms) + W block;
//                 per thread = one sample: project (u = x@W), 16 spline evals,
//                 reconstruct out = x + (y-u)@W^T, write lj partial per (n,k)
//   reduce_lj:    logj[n] = sum_k ljp[n][k]  (fixed order, deterministic)

#define NSAMP   2048
#define NDIMX   3072
#define NTRANSX 3072
#define NBIN    200
#define NKER    192
#define NCLASS  10
#define TPB     256

__device__ int   g_idx[NSAMP];
__device__ int   g_off[NCLASS + 1];
__device__ float g_ljp[NSAMP * NKER];

// ---------------------------------------------------------------------------
// Class-sorted index lists. One block, 1024 threads, 2 samples each.
// ---------------------------------------------------------------------------
__global__ void prep_kernel(const int* __restrict__ label) {
    __shared__ int scnt[NCLASS], soff[NCLASS], sfill[NCLASS];
    int tid = threadIdx.x;
    if (tid < NCLASS) { scnt[tid] = 0; sfill[tid] = 0; }
    __syncthreads();

    int n0 = tid, n1 = tid + 1024;
    int c0 = label[n0];
    int c1 = label[n1];
    atomicAdd(&scnt[c0], 1);
    atomicAdd(&scnt[c1], 1);
    __syncthreads();

    if (tid == 0) {
        int acc = 0;
        for (int c = 0; c < NCLASS; c++) {
            soff[c] = acc;
            g_off[c] = acc;
            acc += scnt[c];
        }
        g_off[NCLASS] = acc;
    }
    __syncthreads();

    int p0 = atomicAdd(&sfill[c0], 1);
    g_idx[soff[c0] + p0] = n0;
    int p1 = atomicAdd(&sfill[c1], 1);
    g_idx[soff[c1] + p1] = n1;
}

// ---------------------------------------------------------------------------
// Main fused kernel. grid = (NKER, NCLASS), 256 threads.
// ---------------------------------------------------------------------------
__global__ void __launch_bounds__(TPB) main_kernel(
    const float* __restrict__ data,   // (NSAMP, NDIMX)
    const float* __restrict__ Wb,     // (NKER, 16, 16)
    const float* __restrict__ kx,     // (NCLASS, NTRANSX, NBIN)
    const float* __restrict__ ky,
    const float* __restrict__ kd,
    float* __restrict__ out)          // (NSAMP, NDIMX)
{
    __shared__ float sx[16 * NBIN];
    __shared__ float sy[16 * NBIN];
    __shared__ float sd[16 * NBIN];
    __shared__ float Wa[256];   // [s][i]  (i contiguous)
    __shared__ float Wt[256];   // [i][j]  (j contiguous)  Wt[i*16+j] = W[j][i]

    const int k   = blockIdx.x;
    const int c   = blockIdx.y;
    const int tid = threadIdx.x;

    // knots for transforms t = 16k .. 16k+15 of class c: one contiguous chunk
    const size_t kb = ((size_t)c * NTRANSX + (size_t)k * 16) * NBIN;
    for (int idx = tid; idx < 16 * NBIN; idx += TPB) {
        sx[idx] = kx[kb + idx];
        sy[idx] = ky[kb + idx];
        sd[idx] = kd[kb + idx];
    }
    {
        int s = tid >> 4, i = tid & 15;
        float v = Wb[k * 256 + tid];   // W[k][s][i]
        Wa[tid] = v;
        Wt[i * 16 + s] = v;
    }
    __syncthreads();

    const int off = g_off[c];
    const int cnt = g_off[c + 1] - off;

    // patch pixel base: k = nh*24 + nw*3 + ch; pixel(j) = base + (j>>2)*96 + (j&3)*3
    const int nh  = k / 24;
    const int rem = k - nh * 24;
    const int nw  = rem / 3;
    const int ch  = rem - nw * 3;
    const int pixbase = nh * 4 * 96 + nw * 4 * 3 + ch;

    const float4* Wa4 = (const float4*)Wa;
    const float4* Wt4 = (const float4*)Wt;

    for (int sbase = 0; sbase < cnt; sbase += TPB) {
        int sidx = sbase + tid;
        if (sidx >= cnt) break;
        const int n = g_idx[off + sidx];
        const float* __restrict__ drow = data + (size_t)n * NDIMX;

        // gather patch pixels
        float xv[16];
#pragma unroll
        for (int j = 0; j < 16; j++) {
            int p = pixbase + (j >> 2) * 96 + (j & 3) * 3;
            xv[j] = __ldg(drow + p);
        }

        // u = x @ W  (16x16), float4 smem broadcasts
        float4 ua0 = make_float4(0.f, 0.f, 0.f, 0.f);
        float4 ua1 = ua0, ua2 = ua0, ua3 = ua0;
#pragma unroll
        for (int s = 0; s < 16; s++) {
            float xs = xv[s];
            float4 w0 = Wa4[s * 4 + 0];
            float4 w1 = Wa4[s * 4 + 1];
            float4 w2 = Wa4[s * 4 + 2];
            float4 w3 = Wa4[s * 4 + 3];
            ua0.x = fmaf(xs, w0.x, ua0.x); ua0.y = fmaf(xs, w0.y, ua0.y);
            ua0.z = fmaf(xs, w0.z, ua0.z); ua0.w = fmaf(xs, w0.w, ua0.w);
            ua1.x = fmaf(xs, w1.x, ua1.x); ua1.y = fmaf(xs, w1.y, ua1.y);
            ua1.z = fmaf(xs, w1.z, ua1.z); ua1.w = fmaf(xs, w1.w, ua1.w);
            ua2.x = fmaf(xs, w2.x, ua2.x); ua2.y = fmaf(xs, w2.y, ua2.y);
            ua2.z = fmaf(xs, w2.z, ua2.z); ua2.w = fmaf(xs, w2.w, ua2.w);
            ua3.x = fmaf(xs, w3.x, ua3.x); ua3.y = fmaf(xs, w3.y, ua3.y);
            ua3.z = fmaf(xs, w3.z, ua3.z); ua3.w = fmaf(xs, w3.w, ua3.w);
        }
        float u[16];
        u[0] = ua0.x; u[1] = ua0.y; u[2]  = ua0.z; u[3]  = ua0.w;
        u[4] = ua1.x; u[5] = ua1.y; u[6]  = ua1.z; u[7]  = ua1.w;
        u[8] = ua2.x; u[9] = ua2.y; u[10] = ua2.z; u[11] = ua2.w;
        u[12] = ua3.x; u[13] = ua3.y; u[14] = ua3.z; u[15] = ua3.w;

        // splines: y_i = RQS_i(u_i), accumulate log|jac|
        float ljsum = 0.f;
        float dyv[16];
#pragma unroll
        for (int i = 0; i < 16; i++) {
            const float* __restrict__ xx  = sx + i * NBIN;
            const float* __restrict__ yyp = sy + i * NBIN;
            const float* __restrict__ ddp = sd + i * NBIN;
            float x  = u[i];
            float lo = xx[0];
            float hi = xx[NBIN - 1];
            float xc = fminf(fmaxf(x, lo), hi);

            // largest kk with xx[kk] <= xc  (xx[0] <= xc guaranteed)
            int kk = 0;
#pragma unroll
            for (int w = 128; w > 0; w >>= 1) {
                int cand = kk + w;
                if (cand <= NBIN - 1) {
                    if (xx[cand] <= xc) kk = cand;
                }
            }
            if (kk > NBIN - 2) kk = NBIN - 2;

            float xk  = xx[kk],  xk1 = xx[kk + 1];
            float yk  = yyp[kk], yk1 = yyp[kk + 1];
            float dk  = ddp[kk], dk1 = ddp[kk + 1];

            float wdt  = xk1 - xk;
            float invw = __fdividef(1.0f, wdt);
            float dyk  = yk1 - yk;
            float s_   = dyk * invw;
            float xi   = (xc - xk) * invw;
            float om   = 1.0f - xi;
            float xi2  = xi * xi;
            float xiom = xi * om;
            float denom = fmaf(fmaf(-2.0f, s_, dk1 + dk), xiom, s_);
            float invd  = __fdividef(1.0f, denom);
            float ys    = fmaf(dyk * invd, fmaf(s_, xi2, dk * xiom), yk);
            float numer = fmaf(dk1, xi2, fmaf(2.0f * s_, xiom, dk * om * om));
            float t1    = s_ * invd;
            float arg   = t1 * t1 * numer;   // = s^2 * numer / denom^2

            float yv, larg;
            if (x < lo) {
                float d0 = ddp[0];
                yv   = fmaf(x - lo, d0, yyp[0]);
                larg = d0;
            } else if (x > hi) {
                float dK = ddp[NBIN - 1];
                yv   = fmaf(x - hi, dK, yyp[NBIN - 1]);
                larg = dK;
            } else {
                yv   = ys;
                larg = arg;
            }
            ljsum += __logf(larg);
            dyv[i] = yv - u[i];
        }

        // reconstruction: out_j = x_j + sum_i dyv_i * W[j][i]
        float4 oa0 = make_float4(0.f, 0.f, 0.f, 0.f);
        float4 oa1 = oa0, oa2 = oa0, oa3 = oa0;
#pragma unroll
        for (int i = 0; i < 16; i++) {
            float dv = dyv[i];
            float4 w0 = Wt4[i * 4 + 0];
            float4 w1 = Wt4[i * 4 + 1];
            float4 w2 = Wt4[i * 4 + 2];
            float4 w3 = Wt4[i * 4 + 3];
            oa0.x = fmaf(dv, w0.x, oa0.x); oa0.y = fmaf(dv, w0.y, oa0.y);
            oa0.z = fmaf(dv, w0.z, oa0.z); oa0.w = fmaf(dv, w0.w, oa0.w);
            oa1.x = fmaf(dv, w1.x, oa1.x); oa1.y = fmaf(dv, w1.y, oa1.y);
            oa1.z = fmaf(dv, w1.z, oa1.z); oa1.w = fmaf(dv, w1.w, oa1.w);
            oa2.x = fmaf(dv, w2.x, oa2.x); oa2.y = fmaf(dv, w2.y, oa2.y);
            oa2.z = fmaf(dv, w2.z, oa2.z); oa2.w = fmaf(dv, w2.w, oa2.w);
            oa3.x = fmaf(dv, w3.x, oa3.x); oa3.y = fmaf(dv, w3.y, oa3.y);
            oa3.z = fmaf(dv, w3.z, oa3.z); oa3.w = fmaf(dv, w3.w, oa3.w);
        }
        float ov[16];
        ov[0] = oa0.x; ov[1] = oa0.y; ov[2]  = oa0.z; ov[3]  = oa0.w;
        ov[4] = oa1.x; ov[5] = oa1.y; ov[6]  = oa1.z; ov[7]  = oa1.w;
        ov[8] = oa2.x; ov[9] = oa2.y; ov[10] = oa2.z; ov[11] = oa2.w;
        ov[12] = oa3.x; ov[13] = oa3.y; ov[14] = oa3.z; ov[15] = oa3.w;

        float* __restrict__ orow = out + (size_t)n * NDIMX;
#pragma unroll
        for (int j = 0; j < 16; j++) {
            int p = pixbase + (j >> 2) * 96 + (j & 3) * 3;
            orow[p] = xv[j] + ov[j];
        }

        g_ljp[n * NKER + k] = ljsum;
    }
}

// ---------------------------------------------------------------------------
// logj[n] = sum over 192 patches (fixed order — deterministic)
// ---------------------------------------------------------------------------
__global__ void reduce_lj(float* __restrict__ logj) {
    int n = blockIdx.x * blockDim.x + threadIdx.x;
    if (n >= NSAMP) return;
    const float4* p = (const float4*)(g_ljp + (size_t)n * NKER);
    float s = 0.f;
#pragma unroll
    for (int q = 0; q < NKER / 4; q++) {
        float4 v = p[q];
        s += v.x + v.y + v.z + v.w;
    }
    logj[n] = s;
}

// ---------------------------------------------------------------------------
extern "C" void kernel_launch(void* const* d_in, const int* in_sizes, int n_in,
                              void* d_out, int out_size) {
    const float* data  = (const float*)d_in[0];
    const int*   label = (const int*)d_in[1];
    const float* Wb    = (const float*)d_in[2];
    const float* kxp   = (const float*)d_in[3];
    const float* kyp   = (const float*)d_in[4];
    const float* kdp   = (const float*)d_in[5];

    float* out  = (float*)d_out;                      // (2048, 3072)
    float* logj = out + (size_t)NSAMP * NDIMX;        // (2048,)

    prep_kernel<<<1, 1024>>>(label);
    main_kernel<<<dim3(NKER, NCLASS), TPB>>>(data, Wb, kxp, kyp, kdp, out);
    reduce_lj<<<(NSAMP + 255) / 256, 256>>>(logj);
}